// round 9
// baseline (speedup 1.0000x reference)
#include <cuda_runtime.h>
#include <cuda_fp16.h>
#include <cstdint>

#define DIM 128

// Capacity limits (problem spec: N = 110000 joint rows, E = 1200000 per matrix).
#define NMAX 131072          // max N
#define EMAX 1310720         // max edges per matrix

// Static scratch (no allocations allowed).
__device__ int   g_cnt[2 * NMAX];              // per-(matrix,row) edge counts
__device__ int   g_cur[2 * NMAX];              // scatter cursors
__device__ __align__(16) int2 g_rowinfo[2 * NMAX]; // slot 2r+m: (start, last_pair_byteoff)
__device__ int   g_counter;                    // scan block-offset counter
__device__ __align__(16) int2 g_edge[2 * EMAX + 6 * NMAX + 8]; // (col_byte_off, val_half2)
__device__ uint2 g_x1h[NMAX * (DIM / 4)];      // fp16 x1: 32 uint2 per row (256 B/row)

// ---------------------------------------------------------------------------
// K1 (fused): build x1 fp32 into out[0] (streaming stores), fp16 copy into
//             g_x1h, histogram edge rows (4 edges per thread via int4).
// ---------------------------------------------------------------------------
__global__ void k_init_hist(const float4* __restrict__ node4,
                            const float4* __restrict__ attri4,
                            float4* __restrict__ out4,
                            const int* __restrict__ r1,
                            const int* __restrict__ r2,
                            long node_f4, long total_f4,
                            int E, int n)
{
    long i = (long)blockIdx.x * blockDim.x + threadIdx.x;

    if (i < total_f4) {
        float4 f = (i < node_f4) ? node4[i] : attri4[i - node_f4];
        __stcs(out4 + i, f);                           // fp32 x1, evict-first
        __half2 h01 = __floats2half2_rn(f.x, f.y);
        __half2 h23 = __floats2half2_rn(f.z, f.w);
        uint2 u;
        u.x = *reinterpret_cast<unsigned*>(&h01);
        u.y = *reinterpret_cast<unsigned*>(&h23);
        g_x1h[i] = u;                                  // fp16 x1 (keep in L2)
    }

    int E4 = E >> 2;
    if ((E & 3) == 0) {
        if (i < 2L * E4) {
            int m = (i < E4) ? 0 : 1;
            long e4 = (m == 0) ? i : (i - E4);
            const int4* rp = reinterpret_cast<const int4*>(m == 0 ? r1 : r2);
            int4 r = __ldg(rp + e4);
            int base = m * n;
            atomicAdd(g_cnt + base + r.x, 1);
            atomicAdd(g_cnt + base + r.y, 1);
            atomicAdd(g_cnt + base + r.z, 1);
            atomicAdd(g_cnt + base + r.w, 1);
        }
    } else {
        long twoE = 2L * E;
        if (i < twoE) {
            int b = (i < E) ? __ldg(r1 + i) : (n + __ldg(r2 + (i - E)));
            atomicAdd(g_cnt + b, 1);
        }
    }
}

// ---------------------------------------------------------------------------
// K2: exclusive scan of counts padded so the LAST PAIR of every row is all
//     zeros: vp = (v+3) & ~1 (even, >= v+1, last 2 slots zero). Writes
//     interleaved rowinfo (start, (vp-2)*8), cursors, and pad edges.
// ---------------------------------------------------------------------------
__global__ void k_scan(int n2, int n)
{
    __shared__ int ws[32];
    __shared__ int base;
    int t = threadIdx.x, lane = t & 31, w = t >> 5;
    int i = blockIdx.x * 1024 + t;
    int v  = (i < n2) ? g_cnt[i] : 0;
    int vp = (v + 3) & ~1;                    // even, last pair fully zero

    int x = vp;
#pragma unroll
    for (int d = 1; d < 32; d <<= 1) {
        int y = __shfl_up_sync(0xffffffffu, x, d);
        if (lane >= d) x += y;
    }
    if (lane == 31) ws[w] = x;
    __syncthreads();
    if (w == 0) {
        int s = ws[lane];
#pragma unroll
        for (int d = 1; d < 32; d <<= 1) {
            int y = __shfl_up_sync(0xffffffffu, s, d);
            if (lane >= d) s += y;
        }
        ws[lane] = s;
    }
    __syncthreads();
    if (t == 0) base = atomicAdd(&g_counter, ws[31]);
    int incl = x + (w > 0 ? ws[w - 1] : 0);
    __syncthreads();
    if (i < n2) {
        int excl = base + incl - vp;          // 2-slot aligned start
        int row = (i < n) ? i : (i - n);
        int m   = (i < n) ? 0 : 1;
        g_rowinfo[2 * row + m] = make_int2(excl, (vp - 2) * 8);
        g_cur[i] = excl;
        for (int p = v; p < vp; p++)          // 1..3 zero pad edges
            g_edge[excl + p] = make_int2(0, 0);
    }
}

// ---------------------------------------------------------------------------
// K3: permute edges into CSR order, 4 edges per thread (vector loads).
// Stores (col byte-offset into g_x1h, val duplicated as half2).
// ---------------------------------------------------------------------------
__device__ __forceinline__ int f2h2_bits(float v)
{
    __half2 h = __float2half2_rn(v);
    return *reinterpret_cast<int*>(&h);
}

__global__ void k_permute(const int* __restrict__ r1, const int* __restrict__ c1,
                          const float* __restrict__ v1,
                          const int* __restrict__ r2, const int* __restrict__ c2,
                          const float* __restrict__ v2,
                          int E, int n)
{
    long i = (long)blockIdx.x * blockDim.x + threadIdx.x;
    int E4 = E >> 2;

    if ((E & 3) == 0) {
        if (i >= 2L * E4) return;
        int m = (i < E4) ? 0 : 1;
        long e4 = (m == 0) ? i : (i - E4);
        const int4*   rp = reinterpret_cast<const int4*>(m == 0 ? r1 : r2);
        const int4*   cp = reinterpret_cast<const int4*>(m == 0 ? c1 : c2);
        const float4* vp = reinterpret_cast<const float4*>(m == 0 ? v1 : v2);
        int4   r = __ldg(rp + e4);
        int4   c = __ldg(cp + e4);
        float4 v = __ldg(vp + e4);
        int base = m * n;
        int p0 = atomicAdd(g_cur + base + r.x, 1);
        int p1 = atomicAdd(g_cur + base + r.y, 1);
        int p2 = atomicAdd(g_cur + base + r.z, 1);
        int p3 = atomicAdd(g_cur + base + r.w, 1);
        g_edge[p0] = make_int2(c.x << 8, f2h2_bits(v.x));
        g_edge[p1] = make_int2(c.y << 8, f2h2_bits(v.y));
        g_edge[p2] = make_int2(c.z << 8, f2h2_bits(v.z));
        g_edge[p3] = make_int2(c.w << 8, f2h2_bits(v.w));
    } else {
        long tot = 2L * E;
        if (i >= tot) return;
        int b, col; float val;
        if (i < E) { b = __ldg(r1 + i);     col = __ldg(c1 + i);     val = __ldg(v1 + i); }
        else       { long e = i - E;
                     b = n + __ldg(r2 + e); col = __ldg(c2 + e);     val = __ldg(v2 + e); }
        int pos = atomicAdd(g_cur + b, 1);
        g_edge[pos] = make_int2(col << 8, f2h2_bits(val));
    }
}

// ---------------------------------------------------------------------------
// K4: gather SpMM. One warp handles row r of BOTH matrices (two independent
// edge streams, shared trip count, pointer clamped to the row's guaranteed
// all-zero last pair -> no divergence, no per-edge selects). Lane owns 4 of
// 128 floats. 2 meta LDG.128 + 4 x LDG.64 in flight per iteration.
// ---------------------------------------------------------------------------
__global__ void __launch_bounds__(256)
k_gather(float* __restrict__ out, int n, long total_f)
{
    int gw   = (int)(((long)blockIdx.x * blockDim.x + threadIdx.x) >> 5);
    int lane = threadIdx.x & 31;
    if (gw >= n) return;

    int4 ri = __ldg(reinterpret_cast<const int4*>(g_rowinfo) + gw);
    // ri.x = startA, ri.y = lastA (byte off of last pair), ri.z/w for matrix 2
    const char* eA = reinterpret_cast<const char*>(g_edge + ri.x);
    const char* eB = reinterpret_cast<const char*>(g_edge + ri.z);
    int lastA = ri.y, lastB = ri.w;
    int kmax  = lastA > lastB ? lastA : lastB;

    const char* xb = reinterpret_cast<const char*>(g_x1h) + lane * 8;

    __half2 a0 = __floats2half2_rn(0.f, 0.f), a1 = a0;   // matrix-1 row
    __half2 b0 = a0, b1 = a0;                             // matrix-2 row

    for (int kb = 0; kb <= kmax; kb += 16) {
        int oa = kb < lastA ? kb : lastA;     // IMNMX clamp to zero pair
        int ob = kb < lastB ? kb : lastB;
        int4 mA = __ldcs(reinterpret_cast<const int4*>(eA + oa));
        int4 mB = __ldcs(reinterpret_cast<const int4*>(eB + ob));

        uint2 xA0 = __ldg(reinterpret_cast<const uint2*>(xb + mA.x));
        uint2 xA1 = __ldg(reinterpret_cast<const uint2*>(xb + mA.z));
        uint2 xB0 = __ldg(reinterpret_cast<const uint2*>(xb + mB.x));
        uint2 xB1 = __ldg(reinterpret_cast<const uint2*>(xb + mB.z));

        __half2 vA0 = *reinterpret_cast<__half2*>(&mA.y);
        __half2 vA1 = *reinterpret_cast<__half2*>(&mA.w);
        __half2 vB0 = *reinterpret_cast<__half2*>(&mB.y);
        __half2 vB1 = *reinterpret_cast<__half2*>(&mB.w);

        a0 = __hfma2(vA0, *reinterpret_cast<__half2*>(&xA0.x), a0);
        a1 = __hfma2(vA0, *reinterpret_cast<__half2*>(&xA0.y), a1);
        b0 = __hfma2(vB0, *reinterpret_cast<__half2*>(&xB0.x), b0);
        b1 = __hfma2(vB0, *reinterpret_cast<__half2*>(&xB0.y), b1);
        a0 = __hfma2(vA1, *reinterpret_cast<__half2*>(&xA1.x), a0);
        a1 = __hfma2(vA1, *reinterpret_cast<__half2*>(&xA1.y), a1);
        b0 = __hfma2(vB1, *reinterpret_cast<__half2*>(&xB1.x), b0);
        b1 = __hfma2(vB1, *reinterpret_cast<__half2*>(&xB1.y), b1);
    }

    float2 fa0 = __half22float2(a0), fa1 = __half22float2(a1);
    float2 fb0 = __half22float2(b0), fb1 = __half22float2(b1);

    float* oA = out + total_f + (long)gw * DIM;          // x2[r]
    __stcs(reinterpret_cast<float4*>(oA) + lane,
           make_float4(fa0.x, fa0.y, fa1.x, fa1.y));
    __stcs(reinterpret_cast<float4*>(oA + total_f) + lane,   // x3[r]
           make_float4(fb0.x, fb0.y, fb1.x, fb1.y));
}

// ---------------------------------------------------------------------------
extern "C" void kernel_launch(void* const* d_in, const int* in_sizes, int n_in,
                              void* d_out, int out_size)
{
    const float* node  = (const float*)d_in[0];
    const float* attri = (const float*)d_in[1];
    const int*   r1    = (const int*)  d_in[2];
    const int*   c1    = (const int*)  d_in[3];
    const float* v1    = (const float*)d_in[4];
    const int*   r2    = (const int*)  d_in[5];
    const int*   c2    = (const int*)  d_in[6];
    const float* v2    = (const float*)d_in[7];
    float* out = (float*)d_out;

    long node_f  = in_sizes[0];
    long attri_f = in_sizes[1];
    long total_f = node_f + attri_f;
    int  E       = in_sizes[2];
    int  n       = (int)(total_f / DIM);
    int  n2      = 2 * n;

    // K0: zero counters (memset nodes are graph-capturable).
    void *p_cnt = nullptr, *p_counter = nullptr;
    cudaGetSymbolAddress(&p_cnt, g_cnt);
    cudaGetSymbolAddress(&p_counter, g_counter);
    cudaMemsetAsync(p_cnt, 0, (size_t)n2 * sizeof(int));
    cudaMemsetAsync(p_counter, 0, sizeof(int));

    // K1: fused copy + fp16 convert + histogram
    {
        long total4 = total_f / 4;
        long histN  = ((E & 3) == 0) ? (2L * (E >> 2)) : (2L * E);
        long end = total4 > histN ? total4 : histN;
        int  threads = 256;
        long blocks = (end + threads - 1) / threads;
        k_init_hist<<<(unsigned)blocks, threads>>>(
            (const float4*)node, (const float4*)attri, (float4*)out,
            r1, r2, node_f / 4, total4, E, n);
    }

    // K2: scan (+ pad-edge zeroing, interleaved rowinfo)
    k_scan<<<(n2 + 1023) / 1024, 1024>>>(n2, n);

    // K3: permute (4 edges/thread, half2 vals)
    {
        long workers = ((E & 3) == 0) ? (2L * (E >> 2)) : (2L * E);
        int  threads = 256;
        long blocks = (workers + threads - 1) / threads;
        k_permute<<<(unsigned)blocks, threads>>>(r1, c1, v1, r2, c2, v2, E, n);
    }

    // K4: gather SpMM (one warp per row-PAIR: both matrices)
    {
        int threads = 256;
        long blocks = ((long)n * 32 + threads - 1) / threads;
        k_gather<<<(unsigned)blocks, threads>>>(out, n, total_f);
    }
}